// round 3
// baseline (speedup 1.0000x reference)
#include <cuda_runtime.h>
#include <stdint.h>

// Problem constants (fixed dataset shapes)
#define NB   64
#define CH   256
#define HH   28
#define WW   28
#define HP   30      // padded height
#define WP   30      // padded width
#define OCB  128     // output channels per block
#define ICB  64      // input-channel chunk per smem stage
#define NCHUNK (CH/ICB)   // 4

// smem layout: x tile 6*30*64 B = 11520 B, weights 128 oc * (9*16 + 1 pad) ints = 74240 B
#define SX_INTS   (6*30*16)        // 2880 ints
#define SW_STRIDE 145              // 9*16 + 1 pad (avoids 32-way bank conflicts)
#define SW_INTS   (OCB*SW_STRIDE)  // 18560 ints
#define SMEM_BYTES ((SX_INTS + SW_INTS) * 4)   // 85760

// ---------------- scratch (device globals; no cudaMalloc allowed) ----------------
__device__ __align__(16) int8_t  g_xs [(size_t)NB*HP*WP*CH];   // (x - z_x) int8, zero-padded, NHWC
__device__ __align__(16) uint8_t g_mid[(size_t)NB*HP*WP*CH];   // conv1 output u8, pad = z_conv1
__device__ __align__(16) int8_t  g_wq1[CH*9*CH];               // w1 as [o][tap][ic] int8
__device__ __align__(16) int8_t  g_wq2[CH*9*CH];               // w2 as [o][tap][ic] int8
__device__ int g_wsum2[CH];                                    // per-oc sum of w2 (for zero-point corr)

__device__ __forceinline__ int dp4a_ss(int a, int b, int c) {
    int d; asm("dp4a.s32.s32 %0, %1, %2, %3;" : "=r"(d) : "r"(a), "r"(b), "r"(c)); return d;
}
__device__ __forceinline__ int dp4a_us(int a, int b, int c) {
    int d; asm("dp4a.u32.s32 %0, %1, %2, %3;" : "=r"(d) : "r"(a), "r"(b), "r"(c)); return d;
}

// ---------------- init: zero xs, fill mid with z_conv1 byte (pad trick) ----------------
__global__ void k_init(const float* __restrict__ pz1) {
    unsigned idx = blockIdx.x * blockDim.x + threadIdx.x;   // 921600 int4 slots
    uint32_t z  = (uint32_t)(int)rintf(*pz1) & 0xFFu;
    uint32_t zp = z * 0x01010101u;
    int4 zv = make_int4((int)zp, (int)zp, (int)zp, (int)zp);
    int4 z0 = make_int4(0, 0, 0, 0);
    ((int4*)g_xs)[idx]  = z0;
    ((int4*)g_mid)[idx] = zv;
}

// ---------------- pack x: NCHW fp32 -> padded NHWC int8 (x - z_x) ----------------
__global__ void k_pack_x(const float* __restrict__ x, const float* __restrict__ pzx) {
    int idx = blockIdx.x * blockDim.x + threadIdx.x;   // exactly NB*HH*WW*CH threads
    float zx = *pzx;
    int c  = idx & 255;
    int t  = idx >> 8;
    int ow = t % WW; t /= WW;
    int oh = t % HH;
    int n  = t / HH;
    float g = x[((n*CH + c)*HH + oh)*WW + ow];
    int v = (int)rintf(__fsub_rn(g, zx));
    g_xs[((n*HP + oh + 1)*WP + ow + 1)*CH + c] = (int8_t)v;
}

// ---------------- pack w: OIHW fp32 -> [o][tap][ic] int8 ----------------
__global__ void k_pack_w(const float* __restrict__ w, int which) {
    int idx = blockIdx.x * blockDim.x + threadIdx.x;   // CH*9*CH threads
    int ic = idx & 255;
    int t  = (idx >> 8) % 9;
    int o  = (idx >> 8) / 9;
    int8_t v = (int8_t)(int)rintf(w[(o*CH + ic)*9 + t]);
    if (which == 0) g_wq1[idx] = v; else g_wq2[idx] = v;
}

// ---------------- per-oc weight sum for w2 (zero-point correction) ----------------
__global__ void k_wsum(const float* __restrict__ w2) {
    __shared__ int red[256];
    int o = blockIdx.x;
    int s = 0;
    for (int j = threadIdx.x; j < 2304; j += 256)
        s += (int)rintf(w2[o*2304 + j]);     // OIHW is contiguous per o: 256*9 = 2304
    red[threadIdx.x] = s;
    __syncthreads();
    for (int d = 128; d > 0; d >>= 1) {
        if (threadIdx.x < d) red[threadIdx.x] += red[threadIdx.x + d];
        __syncthreads();
    }
    if (threadIdx.x == 0) g_wsum2[o] = red[0];
}

// ---------------- fused quantized conv (MODE 0: conv1, MODE 1: conv2 + residual qadd) ----------------
template <int MODE>
__global__ __launch_bounds__(256, 2) void k_conv(
    const float* __restrict__ ps_in,  const float* __restrict__ ps_w,
    const float* __restrict__ ps_out, const float* __restrict__ pz_out,
    const float* __restrict__ pz_in,                      // MODE 1: z_conv1
    const float* __restrict__ ps_x,  const float* __restrict__ ps_add,
    const float* __restrict__ pz_add,
    float* __restrict__ out)
{
    extern __shared__ int smem[];
    int* sxs = smem;                  // [6*30][16] ints (x tile, ICB=64 bytes/pixel)
    int* sws = smem + SX_INTS;        // [OCB][145] ints (weights, padded stride)

    const uint8_t* act = (MODE == 0) ? (const uint8_t*)g_xs : g_mid;
    const int8_t*  wq  = (MODE == 0) ? g_wq1 : g_wq2;

    const int strip  = blockIdx.x;    // 0..6 (4 output rows each)
    const int octile = blockIdx.y;    // 0..1
    const int n      = blockIdx.z;    // image
    const int tid    = threadIdx.x;
    const int r      = tid >> 6;      // local output row 0..3
    const int ocg    = tid & 63;      // 64 groups of 2 oc
    const int oc0    = octile*OCB + ocg*2;
    const int oh     = strip*4 + r;
    const int hbase  = strip*4;       // padded-row base of the 6-row tile

    int acc0[28], acc1[28];
#pragma unroll
    for (int p = 0; p < 28; p++) { acc0[p] = 0; acc1[p] = 0; }

#pragma unroll 1
    for (int chunk = 0; chunk < NCHUNK; chunk++) {
        __syncthreads();
        // load x tile: 6 rows x 30 cols x 64 B = 720 int4
        {
            const int4* gact = (const int4*)act;
            for (int j = tid; j < 6*30*4; j += 256) {
                int q   = j & 3;
                int pix = j >> 2;
                int col = pix % 30;
                int row = pix / 30;
                ((int4*)sxs)[pix*4 + q] =
                    gact[((size_t)(n*HP + hbase + row)*WP + col)*16 + chunk*4 + q];
            }
        }
        // load weight chunk: 128 oc x 9 taps x 16 ints (stride-145 in smem)
        {
            const int* gw = (const int*)wq;
            for (int j = tid; j < OCB*144; j += 256) {
                int oc  = j / 144;
                int rem = j - oc*144;          // t*16 + ic4
                int t9  = rem >> 4;
                int ic4 = rem & 15;
                sws[oc*SW_STRIDE + rem] =
                    gw[((octile*OCB + oc)*9 + t9)*64 + chunk*16 + ic4];
            }
        }
        __syncthreads();

#pragma unroll 1
        for (int ic4 = 0; ic4 < 16; ic4++) {
#pragma unroll
            for (int dr = 0; dr < 3; dr++) {
                int xr[30];
#pragma unroll
                for (int c2 = 0; c2 < 30; c2++)
                    xr[c2] = sxs[((r + dr)*30 + c2)*16 + ic4];   // warp broadcast
#pragma unroll
                for (int dc = 0; dc < 3; dc++) {
                    const int t9 = dr*3 + dc;
                    int w0 = sws[(ocg*2    )*SW_STRIDE + t9*16 + ic4];
                    int w1 = sws[(ocg*2 + 1)*SW_STRIDE + t9*16 + ic4];
#pragma unroll
                    for (int p = 0; p < 28; p++) {
                        if (MODE == 0) {
                            acc0[p] = dp4a_ss(xr[p + dc], w0, acc0[p]);
                            acc1[p] = dp4a_ss(xr[p + dc], w1, acc1[p]);
                        } else {
                            acc0[p] = dp4a_us(xr[p + dc], w0, acc0[p]);
                            acc1[p] = dp4a_us(xr[p + dc], w1, acc1[p]);
                        }
                    }
                }
            }
        }
    }

    // ---------------- epilogue ----------------
    const float M  = __fdiv_rn(__fmul_rn(*ps_in, *ps_w), *ps_out);
    const float zo = *pz_out;

    if (MODE == 0) {
        // requantize -> u8, store into padded mid (interior only)
#pragma unroll
        for (int p = 0; p < 28; p++) {
            float v0 = rintf(__fmul_rn(M, (float)acc0[p])) + zo;
            float v1 = rintf(__fmul_rn(M, (float)acc1[p])) + zo;
            v0 = fminf(fmaxf(v0, 0.f), 255.f);
            v1 = fminf(fmaxf(v1, 0.f), 255.f);
            size_t base = ((size_t)(n*HP + oh + 1)*WP + p + 1)*CH;
            g_mid[base + oc0]     = (uint8_t)v0;
            g_mid[base + oc0 + 1] = (uint8_t)v1;
        }
    } else {
        // zero-point correction (exact integer), requantize, fused residual qadd
        const int izin = (int)rintf(*pz_in);
        const int ws0  = g_wsum2[oc0];
        const int ws1  = g_wsum2[oc0 + 1];
        const float ra = __fdiv_rn(*ps_x,  *ps_add);
        const float rb = __fdiv_rn(*ps_out, *ps_add);
        const float za = *pz_add;
#pragma unroll
        for (int p = 0; p < 28; p++) {
            int a0 = acc0[p] - izin*ws0;
            int a1 = acc1[p] - izin*ws1;
            float v0 = rintf(__fmul_rn(M, (float)a0)) + zo;
            float v1 = rintf(__fmul_rn(M, (float)a1)) + zo;
            v0 = fminf(fmaxf(v0, 0.f), 255.f);
            v1 = fminf(fmaxf(v1, 0.f), 255.f);
            size_t xbase = ((size_t)(n*HP + oh + 1)*WP + p + 1)*CH;
            float xv0 = (float)(int)((const int8_t*)g_xs)[xbase + oc0];
            float xv1 = (float)(int)((const int8_t*)g_xs)[xbase + oc0 + 1];
            float y0 = __fadd_rn(__fmul_rn(ra, xv0), __fmul_rn(rb, __fsub_rn(v0, zo)));
            float y1 = __fadd_rn(__fmul_rn(ra, xv1), __fmul_rn(rb, __fsub_rn(v1, zo)));
            float o0 = fminf(fmaxf(rintf(y0) + za, 0.f), 255.f);
            float o1 = fminf(fmaxf(rintf(y1) + za, 0.f), 255.f);
            out[((size_t)(n*CH + oc0    )*HH + oh)*WW + p] = o0;
            out[((size_t)(n*CH + oc0 + 1)*HH + oh)*WW + p] = o1;
        }
    }
}

// ---------------- launch ----------------
extern "C" void kernel_launch(void* const* d_in, const int* in_sizes, int n_in,
                              void* d_out, int out_size) {
    const float* x    = (const float*)d_in[0];
    const float* w1   = (const float*)d_in[1];
    const float* w2   = (const float*)d_in[2];
    const float* s_x  = (const float*)d_in[3];
    const float* z_x  = (const float*)d_in[4];
    const float* s_w1 = (const float*)d_in[5];
    const float* s_c1 = (const float*)d_in[6];
    const float* z_c1 = (const float*)d_in[7];
    const float* s_w2 = (const float*)d_in[8];
    const float* s_c2 = (const float*)d_in[9];
    const float* z_c2 = (const float*)d_in[10];
    const float* s_ad = (const float*)d_in[11];
    const float* z_ad = (const float*)d_in[12];
    float* out = (float*)d_out;

    cudaFuncSetAttribute(k_conv<0>, cudaFuncAttributeMaxDynamicSharedMemorySize, SMEM_BYTES);
    cudaFuncSetAttribute(k_conv<1>, cudaFuncAttributeMaxDynamicSharedMemorySize, SMEM_BYTES);

    // 1) zero xs pad, fill mid with z_conv1
    k_init<<<(NB*HP*WP*CH/16 + 255)/256, 256>>>(z_c1);
    // 2) pack activations and weights
    k_pack_x<<<NB*HH*WW, 256>>>(x, z_x);                 // 50176 blocks, 256 c per block
    k_pack_w<<<CH*9, 256>>>(w1, 0);
    k_pack_w<<<CH*9, 256>>>(w2, 1);
    k_wsum<<<CH, 256>>>(w2);
    // 3) conv1 (signed dp4a, zero pad, no correction)
    dim3 grid(7, 2, NB);
    k_conv<0><<<grid, 256, SMEM_BYTES>>>(s_x, s_w1, s_c1, z_c1, z_c1, s_x, s_ad, z_ad, nullptr);
    // 4) conv2 (unsigned dp4a, z-pad + wsum correction) + fused residual qadd
    k_conv<1><<<grid, 256, SMEM_BYTES>>>(s_c1, s_w2, s_c2, z_c2, z_c1, s_x, s_ad, z_ad, out);
}